// round 9
// baseline (speedup 1.0000x reference)
#include <cuda_runtime.h>
#include <cuda_bf16.h>

#define NCTA   148           // 1 CTA/SM, fully resident (safe on 148 or 152 SMs)
#define WPB    32            // 1024 threads
#define NWARP  (NCTA * WPB)  // 4736
#define GB     8             // batches per group
#define GCH    6144          // channels per group (GB * 768)
#define MWARPS 192           // 8 batches * 24 warps; each M-warp does 8 dots
#define PWARPS (NWARP - MWARPS)  // 4544 pooling warps in phases

// Scratch + sync state. All values return to their initial state every launch:
// leaf/root reset inline, sense targets end at 0, mflag re-zeroed in prologue,
// d_s/d_h fully rewritten.
__device__ float    d_s[24576];
__device__ float    d_h[6144];
__device__ unsigned leaf_cnt[8];
__device__ unsigned root_cnt;
__device__ unsigned g_sense;
__device__ unsigned mflag[GB];    // monotonic: +24 per group per batch-slot

// Tree grid barrier: 8 leaves (distinct L2 lines/slices) -> root -> sense.
__device__ __forceinline__ void grid_bar(unsigned target, int leaf, unsigned leaf_n) {
    __syncthreads();
    if (threadIdx.x == 0) {
        __threadfence();
        if (atomicAdd(&leaf_cnt[leaf], 1) == leaf_n - 1) {
            leaf_cnt[leaf] = 0;                 // no concurrent arrivals now
            __threadfence();
            if (atomicAdd(&root_cnt, 1) == 7) {
                root_cnt = 0;
                __threadfence();
                *(volatile unsigned*)&g_sense = target;
            }
        }
        while (*(volatile unsigned*)&g_sense != target) __nanosleep(64);
        __threadfence();
    }
    __syncthreads();
}

__device__ __forceinline__ void pool_one(const float4* __restrict__ x4, int ch, int lane) {
    const float4* p = x4 + (size_t)ch * 256;
    float4 v[8];
#pragma unroll
    for (int j = 0; j < 8; j++) v[j] = p[lane + j * 32];
    float sum = 0.0f;
#pragma unroll
    for (int j = 0; j < 8; j++) sum += (v[j].x + v[j].y) + (v[j].z + v[j].w);
#pragma unroll
    for (int o = 16; o; o >>= 1) sum += __shfl_xor_sync(0xffffffffu, sum, o);
    if (lane == 0) d_s[ch] = sum * (1.0f / 1024.0f);
}

__device__ __forceinline__ void scale_one(const float4* __restrict__ x4,
                                          float4* __restrict__ o4,
                                          const float* __restrict__ w2,
                                          const float* __restrict__ b2,
                                          int gidx, int j, int lane) {
    int lb = j / 768;                       // batch slot within group
    if (lane == 0) {
        unsigned thr = 24u * (unsigned)(gidx + 1);
        while (*(volatile unsigned*)&mflag[lb] < thr) __nanosleep(32);
    }
    __syncwarp();
    int b = gidx * GB + lb;
    int c = j - lb * 768;
    const float* hr = d_h + b * 192;
    const float* wr = w2 + (size_t)c * 192;
    float acc = 0.0f;
#pragma unroll
    for (int t = 0; t < 6; t++) { int k = lane + t * 32; acc += hr[k] * wr[k]; }
#pragma unroll
    for (int o = 16; o; o >>= 1) acc += __shfl_xor_sync(0xffffffffu, acc, o);
    float gate = 1.0f / (1.0f + __expf(-(acc + b2[c])));

    size_t ch = (size_t)gidx * GCH + j;
    const float4* p = x4 + ch * 256;
    float4*       q = o4 + ch * 256;
#pragma unroll
    for (int jj = 0; jj < 8; jj++) {
        float4 v = __ldcs(p + lane + jj * 32);   // L2-hot from pool phase
        v.x *= gate; v.y *= gate; v.z *= gate; v.w *= gate;
        __stcs(q + lane + jj * 32, v);
    }
}

__global__ __launch_bounds__(1024, 1)
void se_kernel(const float* __restrict__ x,
               const float* __restrict__ w1,
               const float* __restrict__ b1,
               const float* __restrict__ w2,
               const float* __restrict__ b2,
               float* __restrict__ out) {
    const float4* x4 = reinterpret_cast<const float4*>(x);
    float4*       o4 = reinterpret_cast<float4*>(out);
    int tid  = threadIdx.x;
    int warp = tid >> 5;
    int lane = tid & 31;
    int gw   = blockIdx.x * WPB + warp;           // 0..4735
    int leaf = blockIdx.x & 7;
    unsigned leaf_n = (leaf < 4) ? 19u : 18u;     // 148 = 4*19 + 4*18

    // ---- Prologue: zero M flags (stale 4*24 from previous replay) ----------
    if (blockIdx.x == 0 && tid < GB) mflag[tid] = 0;

    // ---- Prologue: pool group 0 (25 MB DRAM read -> L2) --------------------
    pool_one(x4, gw, lane);
    if (gw + NWARP < GCH) pool_one(x4, gw + NWARP, lane);
    grid_bar(1, leaf, leaf_n);

    // ---- 4 phases: M(g) || P(g+1), then S(g) -------------------------------
    for (int gidx = 0; gidx < 4; gidx++) {
        if (gw < MWARPS) {
            // M: h[b][j] = swish(<s[b,:], w1[j,:]> + b1[j]); 8 dots per warp
            int lb = gw / 24;
            int b  = gidx * GB + lb;
            int j0 = (gw % 24) * 8;
            const float* sr = d_s + b * 768;
            for (int jj = 0; jj < 8; jj++) {
                int j = j0 + jj;
                const float* wr = w1 + (size_t)j * 768;
                float acc = 0.0f;
#pragma unroll
                for (int t = 0; t < 24; t++) { int k = lane + t * 32; acc += sr[k] * wr[k]; }
#pragma unroll
                for (int o = 16; o; o >>= 1) acc += __shfl_xor_sync(0xffffffffu, acc, o);
                if (lane == 0) {
                    float h = acc + b1[j];
                    d_h[b * 192 + j] = h / (1.0f + __expf(-h));
                }
            }
            __threadfence();
            if (lane == 0) atomicAdd(&mflag[lb], 1);
        } else if (gidx < 3) {
            // P(g+1): pool next group's channels
            int i = gw - MWARPS;                       // 0..4543
            pool_one(x4, (gidx + 1) * GCH + i, lane);
            if (i + PWARPS < GCH) pool_one(x4, (gidx + 1) * GCH + i + PWARPS, lane);
        }

        // S(g): gate + scale (x[g] resident in L2 from previous phase)
        scale_one(x4, o4, w2, b2, gidx, gw, lane);
        if (gw + NWARP < GCH) scale_one(x4, o4, w2, b2, gidx, gw + NWARP, lane);

        if (gidx < 3) grid_bar((gidx & 1) ? 1u : 0u, leaf, leaf_n);
        // targets: prologue->1, after phase0->0, phase1->1, phase2->0 (ends 0)
    }
}

// ---------------------------------------------------------------------------
extern "C" void kernel_launch(void* const* d_in, const int* in_sizes, int n_in,
                              void* d_out, int out_size) {
    const float* x  = (const float*)d_in[0];
    const float* w1 = (const float*)d_in[1];
    const float* b1 = (const float*)d_in[2];
    const float* w2 = (const float*)d_in[3];
    const float* b2 = (const float*)d_in[4];
    float* out = (float*)d_out;

    se_kernel<<<NCTA, 1024>>>(x, w1, b1, w2, b2, out);
}

// round 11
// speedup vs baseline: 2.3578x; 2.3578x over previous
#include <cuda_runtime.h>
#include <cuda_bf16.h>

#define B_   32
#define C_   768
#define CR_  192
#define BC_  (B_ * C_)     // 24576
#define BCR_ (B_ * CR_)    // 6144

// Scratch (device globals — no allocation allowed in kernel_launch)
__device__ float d_s[BC_];    // pooled means [B, C]
__device__ float d_h[BCR_];   // hidden (swish) [B, Cr]

// 32-byte L2-persist load (sm_103a: evict_last requires .v8.b32 width).
struct F8 { float a0,a1,a2,a3,a4,a5,a6,a7; };
__device__ __forceinline__ F8 ld_evict_last_32B(const void* p) {
    F8 v;
    asm volatile(
        "ld.global.L2::evict_last.v8.b32 {%0,%1,%2,%3,%4,%5,%6,%7}, [%8];"
        : "=f"(v.a0), "=f"(v.a1), "=f"(v.a2), "=f"(v.a3),
          "=f"(v.a4), "=f"(v.a5), "=f"(v.a6), "=f"(v.a7)
        : "l"(p));
    return v;
}

// ---------------------------------------------------------------------------
// Kernel 1: global average pool. One warp per (b,c) channel.
// 1024 floats = 128 x 32B chunks; 4 chunks/lane, evict_last so x persists in
// L2 until the scale pass.
// ---------------------------------------------------------------------------
__global__ __launch_bounds__(256) void pool_kernel(const float* __restrict__ x) {
    int ch   = (blockIdx.x * 256 + threadIdx.x) >> 5;
    int lane = threadIdx.x & 31;

    const char* base = reinterpret_cast<const char*>(x) + (size_t)ch * 4096;
    float sum = 0.0f;
#pragma unroll
    for (int i = 0; i < 4; i++) {
        F8 v = ld_evict_last_32B(base + (lane + i * 32) * 32);
        sum += ((v.a0 + v.a1) + (v.a2 + v.a3)) + ((v.a4 + v.a5) + (v.a6 + v.a7));
    }
#pragma unroll
    for (int o = 16; o; o >>= 1) sum += __shfl_xor_sync(0xffffffffu, sum, o);
    if (lane == 0) d_s[ch] = sum * (1.0f / 1024.0f);
}

// ---------------------------------------------------------------------------
// Kernel 2: h = swish(s @ w1^T + b1). Warp per (b, j) dot of length 768.
// ---------------------------------------------------------------------------
__global__ __launch_bounds__(256) void mlp1_kernel(const float* __restrict__ w1,
                                                   const float* __restrict__ b1) {
    int gw   = (blockIdx.x * 256 + threadIdx.x) >> 5;   // 0..6143
    int lane = threadIdx.x & 31;
    int j = gw % CR_;
    int b = gw / CR_;

    const float* wr = w1 + (size_t)j * C_;
    const float* sr = d_s + b * C_;
    float acc = 0.0f;
#pragma unroll
    for (int t = 0; t < C_ / 32; t++) {                 // 24 independent loads
        int k = lane + t * 32;
        acc += sr[k] * wr[k];
    }
#pragma unroll
    for (int o = 16; o; o >>= 1) acc += __shfl_xor_sync(0xffffffffu, acc, o);
    if (lane == 0) {
        float h = acc + b1[j];
        d_h[b * CR_ + j] = h / (1.0f + __expf(-h));     // swish
    }
}

// ---------------------------------------------------------------------------
// Kernel 3: fused gate + scale. One CTA per (b,c) channel, REVERSED order so
// the scale pass consumes the MRU tail of pool's L2 stream first. Warp 0
// computes g = sigmoid(<h[b,:], w2[c,:]> + b2[c]) concurrently with the x
// loads. Reads: evict-first (last use). Stores: WRITE-THROUGH (__stwt) so the
// 100 MB output stream does not allocate in L2 and evict x ahead of the reads.
// ---------------------------------------------------------------------------
__global__ __launch_bounds__(256) void scale_kernel(const float* __restrict__ x,
                                                    const float* __restrict__ w2,
                                                    const float* __restrict__ b2,
                                                    float* __restrict__ out) {
    __shared__ float g_sm;
    int ch  = (BC_ - 1) - blockIdx.x;   // reverse traversal
    int tid = threadIdx.x;

    const float4* xp = reinterpret_cast<const float4*>(x) + (size_t)ch * 256 + tid;
    float4 v = __ldcs(xp);              // independent of the gate; starts first

    if (tid < 32) {                     // warp 0: 192-length dot
        int c = ch % C_;
        int b = ch / C_;
        const float* wr = w2 + (size_t)c * CR_;
        const float* hr = d_h + b * CR_;
        float acc = 0.0f;
#pragma unroll
        for (int t = 0; t < CR_ / 32; t++) {
            int k = tid + t * 32;
            acc += hr[k] * wr[k];
        }
#pragma unroll
        for (int o = 16; o; o >>= 1) acc += __shfl_xor_sync(0xffffffffu, acc, o);
        if (tid == 0)
            g_sm = 1.0f / (1.0f + __expf(-(acc + b2[c])));
    }
    __syncthreads();

    float g = g_sm;
    v.x *= g; v.y *= g; v.z *= g; v.w *= g;
    __stwt(reinterpret_cast<float4*>(out) + (size_t)ch * 256 + tid, v);
}

// ---------------------------------------------------------------------------
extern "C" void kernel_launch(void* const* d_in, const int* in_sizes, int n_in,
                              void* d_out, int out_size) {
    const float* x  = (const float*)d_in[0];
    const float* w1 = (const float*)d_in[1];
    const float* b1 = (const float*)d_in[2];
    const float* w2 = (const float*)d_in[3];
    const float* b2 = (const float*)d_in[4];
    float* out = (float*)d_out;

    pool_kernel<<<BC_ / 8, 256>>>(x);            // 3072 CTAs
    mlp1_kernel<<<BCR_ / 8, 256>>>(w1, b1);      // 768 CTAs, warp/dot
    scale_kernel<<<BC_, 256>>>(x, w2, b2, out);  // 24576 CTAs, CTA/channel
}